// round 1
// baseline (speedup 1.0000x reference)
#include <cuda_runtime.h>
#include <cuda_bf16.h>

// CropSplitGT: out[h, w, n] = data[h, w, n] * (w in [x1_n, x2_n] && h in [y1_n, y2_n])
// data layout (H, W, N) row-major, N innermost. rois layout (4, N): [x1; y1; x2; y2].
// Pure HBM-bound elementwise op: float4-vectorize along n (N=400 % 4 == 0).

#define HH 512
#define WW 512
#define NN 400
#define N4 (NN / 4)          // 100 float4 per (h,w) pixel
#define ROW4 (WW * N4)       // 51200 float4 per h row

__global__ __launch_bounds__(128) void crop_split_gt_kernel(
    const float4* __restrict__ data,   // (H, W, N) as float4
    const float*  __restrict__ rois,   // (4, N)
    float4*       __restrict__ out)
{
    const int h = blockIdx.y;
    const int tid = blockIdx.x * blockDim.x + threadIdx.x;  // [0, ROW4)
    if (tid >= ROW4) return;

    const int w  = tid / N4;     // pixel column
    const int n4 = tid - w * N4; // float4 group along n

    const float hf = (float)h;
    const float wf = (float)w;

    // rois planes: x1 at [0,N), y1 at [N,2N), x2 at [2N,3N), y2 at [3N,4N)
    // each plane is 1600 B (16B-aligned), so float4 loads are legal.
    const float4 x1 = __ldg((const float4*)(rois)           + n4);
    const float4 y1 = __ldg((const float4*)(rois + NN)      + n4);
    const float4 x2 = __ldg((const float4*)(rois + 2 * NN)  + n4);
    const float4 y2 = __ldg((const float4*)(rois + 3 * NN)  + n4);

    const long idx = (long)h * ROW4 + tid;
    float4 v = data[idx];

    v.x = (wf >= x1.x && wf <= x2.x && hf >= y1.x && hf <= y2.x) ? v.x : 0.0f;
    v.y = (wf >= x1.y && wf <= x2.y && hf >= y1.y && hf <= y2.y) ? v.y : 0.0f;
    v.z = (wf >= x1.z && wf <= x2.z && hf >= y1.z && hf <= y2.z) ? v.z : 0.0f;
    v.w = (wf >= x1.w && wf <= x2.w && hf >= y1.w && hf <= y2.w) ? v.w : 0.0f;

    out[idx] = v;
}

extern "C" void kernel_launch(void* const* d_in, const int* in_sizes, int n_in,
                              void* d_out, int out_size)
{
    const float4* data = (const float4*)d_in[0];   // (H, W, N) fp32
    const float*  rois = (const float*)d_in[1];    // (4, N) fp32
    // d_in[2] = c (unused by the GT variant)
    float4* out = (float4*)d_out;

    dim3 block(128);
    dim3 grid((ROW4 + 127) / 128, HH);   // 400 x 512 blocks
    crop_split_gt_kernel<<<grid, block>>>(data, rois, out);
}

// round 2
// speedup vs baseline: 1.0156x; 1.0156x over previous
#include <cuda_runtime.h>
#include <cuda_bf16.h>

// CropSplitGT: out[h, w, n] = data[h, w, n] if (w,h) inside roi box n else 0.
// data (H, W, N) row-major, rois (4, N) = [x1; y1; x2; y2].
// HBM-bound. Each thread owns one (w, n4) column and walks 8 h-rows, so the
// integer div, rois loads, and x-mask are hoisted; only y-compares + ld/st
// remain in the loop (half the dynamic instructions of round 1).

#define HH 512
#define WW 512
#define NN 400
#define N4 (NN / 4)          // 100 float4 per pixel
#define ROW4 (WW * N4)       // 51200 float4 per row
#define H_PER 8              // rows per thread
#define GY (HH / H_PER)      // 64

__global__ __launch_bounds__(128) void crop_split_gt_kernel(
    const float4* __restrict__ data,
    const float*  __restrict__ rois,
    float4*       __restrict__ out)
{
    const int tid = blockIdx.x * 128 + threadIdx.x;   // [0, ROW4) exactly
    const int w   = tid / N4;
    const int n4  = tid - w * N4;
    const float wf = (float)w;

    const float4 x1 = __ldg((const float4*)(rois)          + n4);
    const float4 y1 = __ldg((const float4*)(rois + NN)     + n4);
    const float4 x2 = __ldg((const float4*)(rois + 2 * NN) + n4);
    const float4 y2 = __ldg((const float4*)(rois + 3 * NN) + n4);

    // x-mask: fixed for this thread across all rows
    const bool mx0 = (wf >= x1.x) && (wf <= x2.x);
    const bool mx1 = (wf >= x1.y) && (wf <= x2.y);
    const bool mx2 = (wf >= x1.z) && (wf <= x2.z);
    const bool mx3 = (wf >= x1.w) && (wf <= x2.w);

    const int h0 = blockIdx.y * H_PER;
    long idx = (long)h0 * ROW4 + tid;

    #pragma unroll
    for (int i = 0; i < H_PER; ++i) {
        const float hf = (float)(h0 + i);
        float4 v = data[idx];
        v.x = (mx0 && hf >= y1.x && hf <= y2.x) ? v.x : 0.0f;
        v.y = (mx1 && hf >= y1.y && hf <= y2.y) ? v.y : 0.0f;
        v.z = (mx2 && hf >= y1.z && hf <= y2.z) ? v.z : 0.0f;
        v.w = (mx3 && hf >= y1.w && hf <= y2.w) ? v.w : 0.0f;
        out[idx] = v;
        idx += ROW4;
    }
}

extern "C" void kernel_launch(void* const* d_in, const int* in_sizes, int n_in,
                              void* d_out, int out_size)
{
    const float4* data = (const float4*)d_in[0];
    const float*  rois = (const float*)d_in[1];
    float4* out = (float4*)d_out;

    dim3 block(128);
    dim3 grid(ROW4 / 128, GY);   // 400 x 64 blocks
    crop_split_gt_kernel<<<grid, block>>>(data, rois, out);
}

// round 3
// speedup vs baseline: 1.0211x; 1.0054x over previous
#include <cuda_runtime.h>
#include <cuda_bf16.h>

// CropSplitGT: out[h, w, n] = data[h, w, n] if (w,h) inside roi box n else 0.
// data (H, W, N) row-major, rois (4, N) = [x1; y1; x2; y2].
// HBM-bound streaming op. Thread owns one (w, n4) column, walks 8 rows in two
// explicit 4-row batches (4 LDG.128 in flight -> MLP 4), with .cs streaming
// hints since neither stream has any reuse.

#define HH 512
#define WW 512
#define NN 400
#define N4 (NN / 4)          // 100 float4 per pixel
#define ROW4 (WW * N4)       // 51200 float4 per row
#define H_PER 8              // rows per thread
#define BATCH 4              // loads in flight
#define GY (HH / H_PER)      // 64

__global__ __launch_bounds__(128) void crop_split_gt_kernel(
    const float4* __restrict__ data,
    const float*  __restrict__ rois,
    float4*       __restrict__ out)
{
    const int tid = blockIdx.x * 128 + threadIdx.x;   // [0, ROW4) exactly
    const int w   = tid / N4;
    const int n4  = tid - w * N4;
    const float wf = (float)w;

    const float4 x1 = __ldg((const float4*)(rois)          + n4);
    const float4 x2 = __ldg((const float4*)(rois + 2 * NN) + n4);
    // x-mask folded immediately; x1/x2 regs die here
    const bool mx0 = (wf >= x1.x) && (wf <= x2.x);
    const bool mx1 = (wf >= x1.y) && (wf <= x2.y);
    const bool mx2 = (wf >= x1.z) && (wf <= x2.z);
    const bool mx3 = (wf >= x1.w) && (wf <= x2.w);

    const float4 y1 = __ldg((const float4*)(rois + NN)     + n4);
    const float4 y2 = __ldg((const float4*)(rois + 3 * NN) + n4);

    const int h0 = blockIdx.y * H_PER;
    long idx = (long)h0 * ROW4 + tid;

    #pragma unroll
    for (int b = 0; b < H_PER / BATCH; ++b) {
        float4 v[BATCH];
        // phase 1: batch the loads -> 4 independent LDG.128 in flight
        #pragma unroll
        for (int i = 0; i < BATCH; ++i)
            v[i] = __ldcs(&data[idx + (long)i * ROW4]);

        // phase 2: mask + store
        #pragma unroll
        for (int i = 0; i < BATCH; ++i) {
            const float hf = (float)(h0 + b * BATCH + i);
            float4 r = v[i];
            r.x = (mx0 && hf >= y1.x && hf <= y2.x) ? r.x : 0.0f;
            r.y = (mx1 && hf >= y1.y && hf <= y2.y) ? r.y : 0.0f;
            r.z = (mx2 && hf >= y1.z && hf <= y2.z) ? r.z : 0.0f;
            r.w = (mx3 && hf >= y1.w && hf <= y2.w) ? r.w : 0.0f;
            __stcs(&out[idx + (long)i * ROW4], r);
        }
        idx += (long)BATCH * ROW4;
    }
}

extern "C" void kernel_launch(void* const* d_in, const int* in_sizes, int n_in,
                              void* d_out, int out_size)
{
    const float4* data = (const float4*)d_in[0];
    const float*  rois = (const float*)d_in[1];
    float4* out = (float4*)d_out;

    dim3 block(128);
    dim3 grid(ROW4 / 128, GY);   // 400 x 64 blocks
    crop_split_gt_kernel<<<grid, block>>>(data, rois, out);
}

// round 4
// speedup vs baseline: 1.1901x; 1.1655x over previous
#include <cuda_runtime.h>
#include <cuda_bf16.h>
#include <math_constants.h>

// CropSplitGT: out[h, w, n] = data[h, w, n] if (w,h) inside roi box n else 0.
// data (H, W, N) row-major, rois (4, N) = [x1; y1; x2; y2].
//
// Traffic-reduction version: ~90% of outputs are zero (avg box covers ~10% of
// the image). Only READ data when at least one of the thread's 4 ROI
// components is inside; otherwise write zeros without touching data.
// Expected read traffic ~56% of full (32B-sector granularity), total ~78%.
//
// x-mask is folded into the y-ranges (y1 -> +inf when x-mask false) so the
// per-row work is just 8 compares + predicated LDG.128 + selects + STG.128.

#define HH 512
#define WW 512
#define NN 400
#define N4 (NN / 4)          // 100 float4 per pixel
#define ROW4 (WW * N4)       // 51200 float4 per row
#define H_PER 8              // rows per thread
#define GY (HH / H_PER)      // 64

__global__ __launch_bounds__(128) void crop_split_gt_kernel(
    const float4* __restrict__ data,
    const float*  __restrict__ rois,
    float4*       __restrict__ out)
{
    const int tid = blockIdx.x * 128 + threadIdx.x;   // [0, ROW4) exactly
    const int w   = tid / N4;
    const int n4  = tid - w * N4;
    const float wf = (float)w;

    const float4 x1 = __ldg((const float4*)(rois)          + n4);
    const float4 x2 = __ldg((const float4*)(rois + 2 * NN) + n4);
    float4 y1 = __ldg((const float4*)(rois + NN)     + n4);
    float4 y2 = __ldg((const float4*)(rois + 3 * NN) + n4);

    // Fold x-mask into y-range: if w outside [x1,x2], make y-range empty.
    if (!(wf >= x1.x && wf <= x2.x)) y1.x = CUDART_INF_F;
    if (!(wf >= x1.y && wf <= x2.y)) y1.y = CUDART_INF_F;
    if (!(wf >= x1.z && wf <= x2.z)) y1.z = CUDART_INF_F;
    if (!(wf >= x1.w && wf <= x2.w)) y1.w = CUDART_INF_F;

    const int h0 = blockIdx.y * H_PER;
    long idx = (long)h0 * ROW4 + tid;

    #pragma unroll
    for (int i = 0; i < H_PER; ++i) {
        const float hf = (float)(h0 + i);
        const bool b0 = (hf >= y1.x) && (hf <= y2.x);
        const bool b1 = (hf >= y1.y) && (hf <= y2.y);
        const bool b2 = (hf >= y1.z) && (hf <= y2.z);
        const bool b3 = (hf >= y1.w) && (hf <= y2.w);

        float4 r = make_float4(0.0f, 0.0f, 0.0f, 0.0f);
        if (b0 | b1 | b2 | b3) {
            const float4 v = __ldcs(&data[idx]);
            r.x = b0 ? v.x : 0.0f;
            r.y = b1 ? v.y : 0.0f;
            r.z = b2 ? v.z : 0.0f;
            r.w = b3 ? v.w : 0.0f;
        }
        __stcs(&out[idx], r);
        idx += ROW4;
    }
}

extern "C" void kernel_launch(void* const* d_in, const int* in_sizes, int n_in,
                              void* d_out, int out_size)
{
    const float4* data = (const float4*)d_in[0];
    const float*  rois = (const float*)d_in[1];
    float4* out = (float4*)d_out;

    dim3 block(128);
    dim3 grid(ROW4 / 128, GY);   // 400 x 64 blocks
    crop_split_gt_kernel<<<grid, block>>>(data, rois, out);
}

// round 5
// speedup vs baseline: 1.2126x; 1.0189x over previous
#include <cuda_runtime.h>
#include <cuda_bf16.h>
#include <math_constants.h>

// CropSplitGT: out[h, w, n] = data[h, w, n] if (w,h) inside roi box n else 0.
// data (H, W, N) row-major, rois (4, N) = [x1; y1; x2; y2].
//
// Sparse-read version, branch-free: reads use a per-thread PREDICATED
// ld.global.cs.v4 (inline PTX) instead of an if-branch, so ptxas can
// front-batch all 8 row-loads (MLP 8) while skipped lanes generate no
// memory traffic. Writes are dense and mandatory.

#define HH 512
#define WW 512
#define NN 400
#define N4 (NN / 4)          // 100 float4 per pixel
#define ROW4 (WW * N4)       // 51200 float4 per row
#define H_PER 8              // rows per thread
#define GY (HH / H_PER)      // 64

__device__ __forceinline__ float4 ldg_cs_pred(const float4* __restrict__ p,
                                              unsigned pred)
{
    // v stays 0 when pred==0 ("+f" keeps the initializer live-in).
    float4 v = make_float4(0.0f, 0.0f, 0.0f, 0.0f);
    asm("{\n\t"
        ".reg .pred %%pp;\n\t"
        "setp.ne.u32 %%pp, %4, 0;\n\t"
        "@%%pp ld.global.cs.v4.f32 {%0, %1, %2, %3}, [%5];\n\t"
        "}"
        : "+f"(v.x), "+f"(v.y), "+f"(v.z), "+f"(v.w)
        : "r"(pred), "l"(p));
    return v;
}

__global__ __launch_bounds__(128) void crop_split_gt_kernel(
    const float4* __restrict__ data,
    const float*  __restrict__ rois,
    float4*       __restrict__ out)
{
    const int tid = blockIdx.x * 128 + threadIdx.x;   // [0, ROW4) exactly
    const int w   = tid / N4;
    const int n4  = tid - w * N4;
    const float wf = (float)w;

    const float4 x1 = __ldg((const float4*)(rois)          + n4);
    const float4 x2 = __ldg((const float4*)(rois + 2 * NN) + n4);
    float4 y1 = __ldg((const float4*)(rois + NN)     + n4);
    float4 y2 = __ldg((const float4*)(rois + 3 * NN) + n4);

    // Fold x-mask into y-range: if w outside [x1,x2], empty the y-range.
    if (!(wf >= x1.x && wf <= x2.x)) y1.x = CUDART_INF_F;
    if (!(wf >= x1.y && wf <= x2.y)) y1.y = CUDART_INF_F;
    if (!(wf >= x1.z && wf <= x2.z)) y1.z = CUDART_INF_F;
    if (!(wf >= x1.w && wf <= x2.w)) y1.w = CUDART_INF_F;

    const int h0 = blockIdx.y * H_PER;
    const long base = (long)h0 * ROW4 + tid;

    // Phase 1: masks + predicated loads for all 8 rows (branch-free, so
    // ptxas can front-batch the LDGs).
    float4 v[H_PER];
    unsigned m[H_PER];   // packed per-component mask bits
    #pragma unroll
    for (int i = 0; i < H_PER; ++i) {
        const float hf = (float)(h0 + i);
        const unsigned b0 = (hf >= y1.x && hf <= y2.x) ? 1u : 0u;
        const unsigned b1 = (hf >= y1.y && hf <= y2.y) ? 2u : 0u;
        const unsigned b2 = (hf >= y1.z && hf <= y2.z) ? 4u : 0u;
        const unsigned b3 = (hf >= y1.w && hf <= y2.w) ? 8u : 0u;
        m[i] = b0 | b1 | b2 | b3;
        v[i] = ldg_cs_pred(&data[base + (long)i * ROW4], m[i]);
    }

    // Phase 2: blend + store.
    #pragma unroll
    for (int i = 0; i < H_PER; ++i) {
        float4 r = v[i];
        r.x = (m[i] & 1u) ? r.x : 0.0f;
        r.y = (m[i] & 2u) ? r.y : 0.0f;
        r.z = (m[i] & 4u) ? r.z : 0.0f;
        r.w = (m[i] & 8u) ? r.w : 0.0f;
        __stcs(&out[base + (long)i * ROW4], r);
    }
}

extern "C" void kernel_launch(void* const* d_in, const int* in_sizes, int n_in,
                              void* d_out, int out_size)
{
    const float4* data = (const float4*)d_in[0];
    const float*  rois = (const float*)d_in[1];
    float4* out = (float4*)d_out;

    dim3 block(128);
    dim3 grid(ROW4 / 128, GY);   // 400 x 64 blocks
    crop_split_gt_kernel<<<grid, block>>>(data, rois, out);
}